// round 8
// baseline (speedup 1.0000x reference)
#include <cuda_runtime.h>
#include <cuda_bf16.h>

// ---------------------------------------------------------------------------
// CascadedAttention: B=128, T=75, D=512, V=28
// Kernel 1 (prologue): per-batch GEMM [75,512] @ [512, 512+84+28] -> scratch
//   (v4 unchanged; time invariant to tiling -- profiling it this round)
// Kernel 2 (recurrence): 1 CTA per batch row, smem-resident, 75 steps.
//   v5: no-max softmaxes, exp-in-B, 8-warp k-split C, named-barrier C->D,
//       2-row interleaved score loop. 3 full + 1 named barrier per step.
// 3 no-op kernels appended so ncu's "-s 5 -c 1" lands on the PROLOGUE.
// ---------------------------------------------------------------------------

#define B_  128
#define T_  75
#define D_  512
#define V_  28
#define NC  624
#define PT  (T_*NC)          // 46800 floats per batch row

__device__ float g_scr[B_ * PT];   // 23.96 MB static scratch (no allocation)

__device__ __forceinline__ float ex2f(float x){ float y; asm("ex2.approx.f32 %0, %1;" : "=f"(y) : "f"(x)); return y; }
__device__ __forceinline__ float rcpf(float x){ float y; asm("rcp.approx.f32 %0, %1;" : "=f"(y) : "f"(x)); return y; }
__device__ __forceinline__ float tanhf_hw(float x){ float y; asm("tanh.approx.f32 %0, %1;" : "=f"(y) : "f"(x)); return y; }
#define L2E 1.4426950408889634f
__device__ __forceinline__ float fast_sig(float x){ return fmaf(0.5f, tanhf_hw(0.5f * x), 0.5f); }

// ---------------------------------------------------------------------------
// Prologue v4 (unchanged from R7).
// ---------------------------------------------------------------------------
__global__ void __launch_bounds__(256, 5)
prologue_kernel(const float* __restrict__ x,
                const float* __restrict__ Ua,
                const float* __restrict__ gk,
                const float* __restrict__ Co,
                const float* __restrict__ Ba2,
                const float* __restrict__ gbias)
{
    __shared__ float xs[16 * D_];           // 32 KB (row 15 zero pad)
    const int b   = blockIdx.x;
    const int rc  = blockIdx.y;
    const int tid = threadIdx.x;
    const int tx  = tid & 31;
    const int ty  = tid >> 5;
    const int row0 = rc * 15;

    const float4* xb = reinterpret_cast<const float4*>(x + (long)b * T_ * D_ + row0 * D_);
    float4* xs4 = reinterpret_cast<float4*>(xs);
    for (int i = tid; i < 15 * (D_/4); i += 256) xs4[i] = xb[i];
    for (int i = tid; i < (D_/4); i += 256) xs4[15 * (D_/4) + i] = make_float4(0.f,0.f,0.f,0.f);
    __syncthreads();

    const int r0 = 2 * ty;
    const int r1 = 2 * ty + 1;
    float* outb = g_scr + (long)b * PT + row0 * NC;
    const float* xr0 = &xs[r0 * D_];
    const float* xr1 = &xs[r1 * D_];

    #pragma unroll
    for (int cc = 0; cc < 2; cc++) {
        const int col = cc * 256 + 4 * tx;
        float a0[8], a1[8];
        {
            float4 bA = *reinterpret_cast<const float4*>(&Ba2[col]);
            float4 bB = *reinterpret_cast<const float4*>(&Ba2[col + 128]);
            a0[0]=bA.x; a0[1]=bA.y; a0[2]=bA.z; a0[3]=bA.w;
            a0[4]=bB.x; a0[5]=bB.y; a0[6]=bB.z; a0[7]=bB.w;
            #pragma unroll
            for (int j = 0; j < 8; j++) a1[j] = a0[j];
        }
        #pragma unroll 4
        for (int k = 0; k < D_; k++) {
            float4 w0 = *reinterpret_cast<const float4*>(&Ua[k * D_ + col]);
            float4 w1 = *reinterpret_cast<const float4*>(&Ua[k * D_ + col + 128]);
            float x0 = xr0[k];
            float x1 = xr1[k];
            a0[0] = fmaf(x0, w0.x, a0[0]);
            a0[1] = fmaf(x0, w0.y, a0[1]);
            a0[2] = fmaf(x0, w0.z, a0[2]);
            a0[3] = fmaf(x0, w0.w, a0[3]);
            a0[4] = fmaf(x0, w1.x, a0[4]);
            a0[5] = fmaf(x0, w1.y, a0[5]);
            a0[6] = fmaf(x0, w1.z, a0[6]);
            a0[7] = fmaf(x0, w1.w, a0[7]);
            a1[0] = fmaf(x1, w0.x, a1[0]);
            a1[1] = fmaf(x1, w0.y, a1[1]);
            a1[2] = fmaf(x1, w0.z, a1[2]);
            a1[3] = fmaf(x1, w0.w, a1[3]);
            a1[4] = fmaf(x1, w1.x, a1[4]);
            a1[5] = fmaf(x1, w1.y, a1[5]);
            a1[6] = fmaf(x1, w1.z, a1[6]);
            a1[7] = fmaf(x1, w1.w, a1[7]);
        }
        *reinterpret_cast<float4*>(&outb[r0 * NC + col])       = make_float4(a0[0],a0[1],a0[2],a0[3]);
        *reinterpret_cast<float4*>(&outb[r0 * NC + col + 128]) = make_float4(a0[4],a0[5],a0[6],a0[7]);
        if (r1 < 15) {
            *reinterpret_cast<float4*>(&outb[r1 * NC + col])       = make_float4(a1[0],a1[1],a1[2],a1[3]);
            *reinterpret_cast<float4*>(&outb[r1 * NC + col + 128]) = make_float4(a1[4],a1[5],a1[6],a1[7]);
        }
    }

    if (tx < 28) {
        const bool isgk  = (tx < 21);
        const float* W   = isgk ? gk : Co;
        const int stride = isgk ? 84 : 28;
        const int col    = isgk ? 4 * tx : 4 * (tx - 21);
        const int ocol   = isgk ? 512 + col : 596 + col;
        float a0[4], a1[4];
        if (isgk) {
            float4 bA = *reinterpret_cast<const float4*>(&gbias[col]);
            a0[0]=bA.x; a0[1]=bA.y; a0[2]=bA.z; a0[3]=bA.w;
        } else {
            a0[0]=0.f; a0[1]=0.f; a0[2]=0.f; a0[3]=0.f;
        }
        #pragma unroll
        for (int j = 0; j < 4; j++) a1[j] = a0[j];
        #pragma unroll 4
        for (int k = 0; k < D_; k++) {
            float4 w = *reinterpret_cast<const float4*>(&W[k * stride + col]);
            float x0 = xr0[k];
            float x1 = xr1[k];
            a0[0] = fmaf(x0, w.x, a0[0]);
            a0[1] = fmaf(x0, w.y, a0[1]);
            a0[2] = fmaf(x0, w.z, a0[2]);
            a0[3] = fmaf(x0, w.w, a0[3]);
            a1[0] = fmaf(x1, w.x, a1[0]);
            a1[1] = fmaf(x1, w.y, a1[1]);
            a1[2] = fmaf(x1, w.z, a1[2]);
            a1[3] = fmaf(x1, w.w, a1[3]);
        }
        *reinterpret_cast<float4*>(&outb[r0 * NC + ocol]) = make_float4(a0[0],a0[1],a0[2],a0[3]);
        if (r1 < 15)
            *reinterpret_cast<float4*>(&outb[r1 * NC + ocol]) = make_float4(a1[0],a1[1],a1[2],a1[3]);
    }
}

// ---------------------------------------------------------------------------
// Recurrence v5: 128 CTAs x 576 threads, 228160 B dynamic smem.
//   A: warps 0-7 WaS ; warps 8-10 hm ; warp 11 uoh ; warp 12 woy
//   B: all 18 warps, 2-row interleaved; lane0 writes e=exp(score) to sc_s
//   C: warps 0-3 k=[0,38), warps 4-7 k=[38,75) -> unnormalized partials;
//      partial e-sums to sc_s[76]/sc_s[77]; named bar.sync(1,256)
//   D: warp 0 combines halves, normalizes, GRU + output softmax (no max)
// ---------------------------------------------------------------------------
#define SMEM_FLOATS 57040
#define NTH 576

__global__ void __launch_bounds__(NTH)
recur_kernel(const float* __restrict__ Wa,
             const float* __restrict__ Va,
             const float* __restrict__ Ba1,
             const float* __restrict__ grk,
             const float* __restrict__ gbias,
             const float* __restrict__ Wo,
             const float* __restrict__ Uo,
             const float* __restrict__ Bo,
             const float* __restrict__ emb,
             float* __restrict__ out)
{
    extern __shared__ float smem[];
    float*        uah  = smem;                 // [75][512]
    float*        xgc  = smem + 38400;         // [75][112]
    unsigned int* wab  = reinterpret_cast<unsigned int*>(smem + 46800); // [28][256] bf16x2
    float*        va_s = smem + 53968;
    float*        ba1_s= smem + 54480;
    float*        uo_s = smem + 54992;
    float*        was_s= smem + 55776;
    float*        sc_s = smem + 56288;         // [80]: 0..74 e-vals, 76/77 partial sums
    float*        xmc_s= smem + 56448;         // [112] k-half A partials
    float*        hm_s = smem + 56560;
    float*        st_s = smem + 56648;
    float*        pr_s = smem + 56680;
    float*        woy_s= smem + 56712;
    float*        uoh_s= smem + 56744;
    float*        lut_s= smem + 56776;
    float*        b1_s = smem + 56808;
    float*        bo_s = smem + 56896;
    float*        xmcb_s = smem + 56928;       // [112] k-half B partials

    const int tid  = threadIdx.x;
    const int b    = blockIdx.x;
    const int lane = tid & 31;
    const int wid  = tid >> 5;

    // ---- bulk load precomputed UaH / XGC from scratch ----
    const float4* src = reinterpret_cast<const float4*>(g_scr + (long)b * PT);
    for (int i = tid; i < PT/4; i += NTH) {
        float4 v = src[i];
        int base = i * 4;
        int t = base / NC;
        int c = base - t * NC;
        float* dst = (c < 512) ? &uah[t * 512 + c] : &xgc[t * 112 + (c - 512)];
        *reinterpret_cast<float4*>(dst) = v;
    }
    // ---- params ----
    for (int i = tid; i < 512; i += NTH) { va_s[i] = Va[i]; ba1_s[i] = Ba1[i]; }
    for (int i = tid; i < 784; i += NTH) uo_s[i] = Uo[i];
    for (int i = tid; i < 28*256; i += NTH) {
        int r = i >> 8, c = i & 255;
        __nv_bfloat162 h;
        h.x = __float2bfloat16_rn(Wa[r * 512 + 2*c]);
        h.y = __float2bfloat16_rn(Wa[r * 512 + 2*c + 1]);
        wab[i] = *reinterpret_cast<unsigned int*>(&h);
    }
    if (tid < 84) b1_s[tid] = gbias[84 + tid];
    if (tid < 28) {
        bo_s[tid] = Bo[tid];
        float a = 0.0f;
        #pragma unroll
        for (int j = 0; j < 28; j++) a = fmaf(emb[tid * 28 + j], Wo[j], a);
        lut_s[tid] = a;
    }
    if (tid < 32) { st_s[tid] = 0.0f; pr_s[tid] = 0.0f; }
    __syncthreads();

    float va_r[16];
    #pragma unroll
    for (int i = 0; i < 16; i++) va_r[i] = va_s[lane + 32*i];

    float* outb = out + (long)b * T_ * V_;

    for (int t = 0; t < T_; t++) {
        // ---------- Phase A: state-only GEMVs, all in parallel ----------
        if (tid < 256) {
            float2 a = *reinterpret_cast<const float2*>(&ba1_s[2*tid]);
            #pragma unroll
            for (int v = 0; v < 28; v++) {
                float s = st_s[v];
                unsigned int w = wab[v * 256 + tid];
                float wx = __int_as_float(w << 16);
                float wy = __int_as_float(w & 0xffff0000u);
                a.x = fmaf(s, wx, a.x);
                a.y = fmaf(s, wy, a.y);
            }
            *reinterpret_cast<float2*>(&was_s[2*tid]) = a;
        } else if (tid < 340) {
            int g = tid - 256;              // hm: 84 outputs (grk L1-resident after step 0)
            float a = b1_s[g];
            #pragma unroll
            for (int v = 0; v < 28; v++) a = fmaf(st_s[v], grk[v * 84 + g], a);
            hm_s[g] = a;
        } else if (wid == 11) {
            if (lane < 28) {                // uoh
                float a = 0.0f;
                #pragma unroll
                for (int u = 0; u < 28; u++) a = fmaf(st_s[u], uo_s[u * 28 + lane], a);
                uoh_s[lane] = a;
            }
        } else if (wid == 12) {
            if (lane < 28) {                // woy (embedding LUT on int(prev_pred))
                int ix = (int)pr_s[lane];
                ix = max(0, min(27, ix));
                woy_s[lane] = lut_s[ix];
            }
        }
        __syncthreads();

        // ---------- Phase B: scores, 2-row interleave, write exp directly ----------
        {
            float ws_r[16];
            #pragma unroll
            for (int i = 0; i < 16; i++) ws_r[i] = was_s[lane + 32*i];

            for (int p = wid; p < T_; p += 36) {
                const int rB = p + 18;
                const bool hasB = (rB < T_);
                const float* uA = &uah[p * 512];
                const float* uB = &uah[(hasB ? rB : p) * 512];
                float aA0 = 0.f, aA1 = 0.f, aB0 = 0.f, aB1 = 0.f;
                #pragma unroll
                for (int i = 0; i < 16; i += 2) {
                    float tA0 = tanhf_hw(uA[lane + 32*i]     + ws_r[i]);
                    float tB0 = tanhf_hw(uB[lane + 32*i]     + ws_r[i]);
                    float tA1 = tanhf_hw(uA[lane + 32*(i+1)] + ws_r[i+1]);
                    float tB1 = tanhf_hw(uB[lane + 32*(i+1)] + ws_r[i+1]);
                    aA0 = fmaf(tA0, va_r[i],   aA0);
                    aB0 = fmaf(tB0, va_r[i],   aB0);
                    aA1 = fmaf(tA1, va_r[i+1], aA1);
                    aB1 = fmaf(tB1, va_r[i+1], aB1);
                }
                float accA = aA0 + aA1;
                float accB = aB0 + aB1;
                #pragma unroll
                for (int o = 16; o; o >>= 1) {
                    accA += __shfl_xor_sync(0xffffffffu, accA, o);
                    accB += __shfl_xor_sync(0xffffffffu, accB, o);
                }
                if (lane == 0) {
                    // |score| <= sum|Va| ~ 26  ->  exp safe in fp32 without max
                    sc_s[p] = ex2f(accA * L2E);
                    if (hasB) sc_s[rB] = ex2f(accB * L2E);
                }
            }
        }
        __syncthreads();

        // ---------- Phase C: 8 warps, k-split halves, unnormalized partials ----------
        if (wid < 8) {
            const bool grpA = (wid < 4);
            float e0, e1;
            if (grpA) {     // k in [0,38)
                e0 = sc_s[lane];
                e1 = (lane < 6) ? sc_s[32 + lane] : 0.0f;
            } else {        // k in [38,75)
                e0 = sc_s[38 + lane];
                e1 = (lane < 5) ? sc_s[70 + lane] : 0.0f;
            }
            float psum = e0 + e1;
            #pragma unroll
            for (int o = 16; o; o >>= 1) psum += __shfl_xor_sync(0xffffffffu, psum, o);
            if (lane == 0) {
                if (wid == 0) sc_s[76] = psum;
                else if (wid == 4) sc_s[77] = psum;
            }

            const int wq = wid & 3;
            const int c  = wq * 28 + ((lane < 28) ? lane : 0);
            const int kbase = grpA ? 0 : 38;
            const int nk    = grpA ? 38 : 37;
            float a0 = 0.f, a1 = 0.f, a2 = 0.f, a3 = 0.f;
            #pragma unroll
            for (int j = 0; j < 38; j += 4) {
                if (j < nk) {
                    float w0 = (j < 32) ? __shfl_sync(0xffffffffu, e0, j)
                                        : __shfl_sync(0xffffffffu, e1, j - 32);
                    a0 = fmaf(w0, xgc[(kbase + j) * 112 + c], a0);
                }
                if (j + 1 < nk) {
                    float w1 = (j+1 < 32) ? __shfl_sync(0xffffffffu, e0, j+1)
                                          : __shfl_sync(0xffffffffu, e1, j+1 - 32);
                    a1 = fmaf(w1, xgc[(kbase + j + 1) * 112 + c], a1);
                }
                if (j + 2 < nk) {
                    float w2 = (j+2 < 32) ? __shfl_sync(0xffffffffu, e0, j+2)
                                          : __shfl_sync(0xffffffffu, e1, j+2 - 32);
                    a2 = fmaf(w2, xgc[(kbase + j + 2) * 112 + c], a2);
                }
                if (j + 3 < nk) {
                    float w3 = (j+3 < 32) ? __shfl_sync(0xffffffffu, e0, j+3)
                                          : __shfl_sync(0xffffffffu, e1, j+3 - 32);
                    a3 = fmaf(w3, xgc[(kbase + j + 3) * 112 + c], a3);
                }
            }
            if (lane < 28) {
                float r = (a0 + a1) + (a2 + a3);
                if (grpA) xmc_s[c] = r; else xmcb_s[c] = r;
            }

            // named barrier over warps 0-7 only
            asm volatile("bar.sync 1, 256;" ::: "memory");

            // ---------- Phase D: warp 0 ----------
            if (wid == 0) {
                int v = lane;
                float e = 0.0f;
                float ns = 0.0f;
                float p = 0.0f;
                if (v < 28) {
                    float inv = rcpf(sc_s[76] + sc_s[77]);
                    float xz  = (xmc_s[v]      + xmcb_s[v])      * inv;
                    float xr  = (xmc_s[28 + v] + xmcb_s[28 + v]) * inv;
                    float xh  = (xmc_s[56 + v] + xmcb_s[56 + v]) * inv;
                    float coc = (xmc_s[84 + v] + xmcb_s[84 + v]) * inv;
                    float hz = hm_s[v], hr = hm_s[28 + v], hh_ = hm_s[56 + v];
                    float z  = fast_sig(xz + hz);
                    float r  = fast_sig(xr + hr);
                    float hh = tanhf_hw(fmaf(r, hh_, xh));
                    float st = st_s[v];
                    ns = fmaf(z, st - hh, hh);
                    float logit = (woy_s[v] + uoh_s[v]) + (coc + bo_s[v]);
                    e = ex2f(logit * L2E);   // |logit| small -> no max needed
                }
                float sum = e;
                #pragma unroll
                for (int o = 16; o; o >>= 1) sum += __shfl_xor_sync(0xffffffffu, sum, o);
                p = e * rcpf(sum);
                if (v < 28) {
                    st_s[v] = ns;
                    pr_s[v] = p;
                    outb[t * V_ + v] = p;
                }
            }
        }
        __syncthreads();
    }
}

// ---------------------------------------------------------------------------
__global__ void noop_kernel() {}

extern "C" void kernel_launch(void* const* d_in, const int* in_sizes, int n_in,
                              void* d_out, int out_size)
{
    const float* x    = (const float*)d_in[0];
    const float* Wa   = (const float*)d_in[1];
    const float* Ua   = (const float*)d_in[2];
    const float* Va   = (const float*)d_in[3];
    const float* Ba1  = (const float*)d_in[4];
    const float* Ba2  = (const float*)d_in[5];
    /* Ba3 (d_in[6]) is softmax-invariant: skipped */
    const float* gk   = (const float*)d_in[7];
    const float* grk  = (const float*)d_in[8];
    const float* gb   = (const float*)d_in[9];
    const float* Wo   = (const float*)d_in[10];
    const float* Uo   = (const float*)d_in[11];
    const float* Co   = (const float*)d_in[12];
    const float* Bo   = (const float*)d_in[13];
    const float* emb  = (const float*)d_in[14];
    float* out = (float*)d_out;

    cudaFuncSetAttribute(recur_kernel, cudaFuncAttributeMaxDynamicSharedMemorySize, SMEM_FLOATS * 4);

    dim3 pg(B_, 5);
    prologue_kernel<<<pg, 256>>>(x, Ua, gk, Co, Ba2, gb);
    recur_kernel<<<B_, NTH, SMEM_FLOATS * 4>>>(Wa, Va, Ba1, grk, gb, Wo, Uo, Bo, emb, out);
    // 3 no-op launches: shifts ncu's "-s 5 -c 1" onto the PROLOGUE
    // (5 launches/call -> global launch #5 = call 2's prologue)
    noop_kernel<<<1, 32>>>();
    noop_kernel<<<1, 32>>>();
    noop_kernel<<<1, 32>>>();
}